// round 1
// baseline (speedup 1.0000x reference)
#include <cuda_runtime.h>
#include <math.h>

#define N_NODES 50000
#define N_EDGES 800000
#define ET (N_EDGES + N_NODES)
#define HEADS 4
#define OUT_CH 32
#define TOPK 8
#define MAXDEG 256
#define NB_SCAN ((N_NODES + 1023) / 1024)

// ---------------- scratch (static __device__ per allocation rules) ----------
__device__ __align__(16) float g_h[N_NODES * 128];   // 25.6 MB
__device__ float g_si[N_NODES * HEADS];
__device__ float g_sj[N_NODES * HEADS];
__device__ int   g_deg[N_NODES + 1];
__device__ int   g_off[N_NODES + 1];
__device__ int   g_cur[N_NODES];
__device__ int   g_col[ET];
__device__ int   g_bsum[NB_SCAN + 1];

// ---------------- CSR build ----------------
__global__ void k_init() {
    int i = blockIdx.x * blockDim.x + threadIdx.x;
    if (i < N_NODES) { g_deg[i] = 1; g_cur[i] = 0; }   // self-loop counted
}

__global__ void k_hist(const int* __restrict__ ei) {
    int e = blockIdx.x * blockDim.x + threadIdx.x;
    if (e < N_EDGES) atomicAdd(&g_deg[ei[e]], 1);
}

__global__ void k_scan1() {
    __shared__ int sh[1024];
    int tid = threadIdx.x;
    int i = blockIdx.x * 1024 + tid;
    int v = (i < N_NODES) ? g_deg[i] : 0;
    sh[tid] = v;
    __syncthreads();
    #pragma unroll
    for (int o = 1; o < 1024; o <<= 1) {
        int t = (tid >= o) ? sh[tid - o] : 0;
        __syncthreads();
        if (tid >= o) sh[tid] += t;
        __syncthreads();
    }
    if (i < N_NODES) g_off[i] = sh[tid] - v;          // exclusive within block
    if (tid == 1023) g_bsum[blockIdx.x] = sh[1023];   // block total
}

__global__ void k_scan2() {
    if (threadIdx.x == 0 && blockIdx.x == 0) {
        int run = 0;
        for (int b = 0; b < NB_SCAN; b++) {
            int t = g_bsum[b];
            g_bsum[b] = run;
            run += t;
        }
    }
}

__global__ void k_scan3() {
    int i = blockIdx.x * 1024 + threadIdx.x;
    if (i < N_NODES) g_off[i] += g_bsum[i >> 10];
    if (i == 0) g_off[N_NODES] = ET;
}

__global__ void k_scatter(const int* __restrict__ ei) {
    int idx = blockIdx.x * blockDim.x + threadIdx.x;
    if (idx >= ET) return;
    int r, c;
    if (idx < N_EDGES) { r = ei[idx]; c = ei[N_EDGES + idx]; }
    else               { r = idx - N_EDGES; c = r; }          // self-loop
    int p = g_off[r] + atomicAdd(&g_cur[r], 1);
    g_col[p] = c;
}

// ---------------- GEMM: h = x @ W  (50000x128 @ 128x128, fp32) ------------
__global__ void k_gemm(const float* __restrict__ x, const float* __restrict__ W) {
    __shared__ float Xs[64][17];
    __shared__ __align__(16) float Ws[16][128];
    int m0 = blockIdx.x * 64;
    int tid = threadIdx.x;
    int tx = tid & 15;        // 16 col-groups * 8 cols
    int ty = tid >> 4;        // 16 row-groups * 4 rows
    int lr = tid >> 2;        // 0..63 : Xs load row
    int lk = (tid & 3) << 2;  // 0,4,8,12 : Xs load k-offset
    int wr = tid >> 4;        // 0..15 : Ws load row
    int wc = (tid & 15) << 3; // 0..120 : Ws load col

    float acc[4][8];
    #pragma unroll
    for (int i = 0; i < 4; i++)
        #pragma unroll
        for (int j = 0; j < 8; j++) acc[i][j] = 0.f;

    for (int kb = 0; kb < 128; kb += 16) {
        int row = m0 + lr;
        float4 xv = make_float4(0.f, 0.f, 0.f, 0.f);
        if (row < N_NODES)
            xv = *(const float4*)&x[row * 128 + kb + lk];
        Xs[lr][lk + 0] = xv.x; Xs[lr][lk + 1] = xv.y;
        Xs[lr][lk + 2] = xv.z; Xs[lr][lk + 3] = xv.w;

        float4 w0 = *(const float4*)&W[(kb + wr) * 128 + wc];
        float4 w1 = *(const float4*)&W[(kb + wr) * 128 + wc + 4];
        *(float4*)&Ws[wr][wc]     = w0;
        *(float4*)&Ws[wr][wc + 4] = w1;
        __syncthreads();

        #pragma unroll
        for (int kk = 0; kk < 16; kk++) {
            float a[4];
            #pragma unroll
            for (int i = 0; i < 4; i++) a[i] = Xs[ty * 4 + i][kk];
            float4 b0 = *(const float4*)&Ws[kk][tx * 8];
            float4 b1 = *(const float4*)&Ws[kk][tx * 8 + 4];
            float b[8] = {b0.x, b0.y, b0.z, b0.w, b1.x, b1.y, b1.z, b1.w};
            #pragma unroll
            for (int i = 0; i < 4; i++)
                #pragma unroll
                for (int j = 0; j < 8; j++)
                    acc[i][j] += a[i] * b[j];
        }
        __syncthreads();
    }

    #pragma unroll
    for (int i = 0; i < 4; i++) {
        int row = m0 + ty * 4 + i;
        if (row < N_NODES) {
            float4 o0 = make_float4(acc[i][0], acc[i][1], acc[i][2], acc[i][3]);
            float4 o1 = make_float4(acc[i][4], acc[i][5], acc[i][6], acc[i][7]);
            *(float4*)&g_h[row * 128 + tx * 8]     = o0;
            *(float4*)&g_h[row * 128 + tx * 8 + 4] = o1;
        }
    }
}

// ---------------- per-node scores: s_i, s_j --------------------------------
__global__ void k_scores(const float* __restrict__ att) {
    int gt = blockIdx.x * blockDim.x + threadIdx.x;
    int w = gt >> 5;               // node
    int lane = gt & 31;
    if (w >= N_NODES) return;
    float4 hv = *(const float4*)&g_h[w * 128 + lane * 4];
    int head = lane >> 3;
    int cbase = (lane & 7) * 4;
    const float* ai = att + head * (2 * OUT_CH) + cbase;
    const float* aj = ai + OUT_CH;
    float pi = hv.x * ai[0] + hv.y * ai[1] + hv.z * ai[2] + hv.w * ai[3];
    float pj = hv.x * aj[0] + hv.y * aj[1] + hv.z * aj[2] + hv.w * aj[3];
    #pragma unroll
    for (int o = 4; o; o >>= 1) {
        pi += __shfl_xor_sync(0xffffffffu, pi, o);
        pj += __shfl_xor_sync(0xffffffffu, pj, o);
    }
    if ((lane & 7) == 0) {
        g_si[w * HEADS + head] = pi;
        g_sj[w * HEADS + head] = pj;
    }
}

// ---------------- top-k + softmax + aggregate + ELU ------------------------
#define AWARPS 8
__global__ void k_agg(float* __restrict__ out) {
    __shared__ float she[AWARPS][MAXDEG];
    __shared__ int   shc[AWARPS][MAXDEG];
    int wib = threadIdx.x >> 5;
    int lane = threadIdx.x & 31;
    int gw = blockIdx.x * AWARPS + wib;        // (node, head) pair id
    if (gw >= N_NODES * HEADS) return;
    int node = gw >> 2;
    int head = gw & 3;

    int start = g_off[node];
    int deg = g_off[node + 1] - start;
    int d = min(deg, MAXDEG);
    float si = g_si[node * HEADS + head];

    for (int i = lane; i < d; i += 32) {
        int c = g_col[start + i];
        float e = si + g_sj[c * HEADS + head];
        e = (e > 0.f) ? e : 0.2f * e;          // leaky_relu(0.2)
        she[wib][i] = e;
        shc[wib][i] = c;
    }
    __syncwarp();

    int k = min(d, TOPK);
    float ev[TOPK];
    int   ec[TOPK];
    #pragma unroll
    for (int r = 0; r < TOPK; r++) { ev[r] = 0.f; ec[r] = 0; }

    // exact multiset top-k: 8 rounds of warp argmax + remove one instance
    #pragma unroll
    for (int r = 0; r < TOPK; r++) {
        if (r < k) {
            float best = -INFINITY; int bi = -1;
            for (int i = lane; i < d; i += 32) {
                float v = she[wib][i];
                if (v > best) { best = v; bi = i; }
            }
            #pragma unroll
            for (int o = 16; o; o >>= 1) {
                float ob = __shfl_down_sync(0xffffffffu, best, o);
                int   oi = __shfl_down_sync(0xffffffffu, bi, o);
                if (ob > best) { best = ob; bi = oi; }
            }
            best = __shfl_sync(0xffffffffu, best, 0);
            bi   = __shfl_sync(0xffffffffu, bi, 0);
            ev[r] = best;
            ec[r] = shc[wib][bi];
            if (lane == 0) she[wib][bi] = -INFINITY;
            __syncwarp();
        }
    }

    float maxe = ev[0];
    float sum = 0.f, acc = 0.f;
    #pragma unroll
    for (int r = 0; r < TOPK; r++) {
        if (r < k) {
            float p = expf(ev[r] - maxe);
            sum += p;
            acc += p * g_h[ec[r] * 128 + head * OUT_CH + lane];
        }
    }
    float o = acc / sum;
    out[node * 128 + head * OUT_CH + lane] = (o > 0.f) ? o : expm1f(o);
}

// ---------------- launch ----------------------------------------------------
extern "C" void kernel_launch(void* const* d_in, const int* in_sizes, int n_in,
                              void* d_out, int out_size) {
    const float* x   = (const float*)d_in[0];
    const float* W   = (const float*)d_in[1];
    const float* att = (const float*)d_in[2];
    const int*   ei  = (const int*)d_in[3];
    float* out = (float*)d_out;

    k_init<<<(N_NODES + 255) / 256, 256>>>();
    k_hist<<<(N_EDGES + 255) / 256, 256>>>(ei);
    k_scan1<<<NB_SCAN, 1024>>>();
    k_scan2<<<1, 32>>>();
    k_scan3<<<NB_SCAN, 1024>>>();
    k_scatter<<<(ET + 255) / 256, 256>>>(ei);
    k_gemm<<<(N_NODES + 63) / 64, 256>>>(x, W);
    k_scores<<<(N_NODES * 32 + 255) / 256, 256>>>(att);
    k_agg<<<(N_NODES * HEADS + AWARPS - 1) / AWARPS, 256>>>(out);
}